// round 2
// baseline (speedup 1.0000x reference)
#include <cuda_runtime.h>

// QLayerNorm: B=4, S=8192, D=1024, fp32.
// One CTA per row. 256 threads/CTA, each handling 4 contiguous floats (float4).
// Single pass: load row into registers, block-reduce sum & sumsq, compute
// mean/var, then the reference's EXACT 4-step recurrence for "std":
//   l1 = (a/a + a)*0.5 ; l_{k+1} = (l_k/a + a)*0.5   (divisor is always a!)
// then fused normalize * weight + bias store.

#define D 1024
#define THREADS 256
#define VEC 4            // floats per thread (D / THREADS)
#define EPS 5e-05f

__global__ __launch_bounds__(THREADS) void qlayernorm_kernel(
    const float* __restrict__ x,
    const float* __restrict__ weight,
    const float* __restrict__ bias,
    float* __restrict__ out)
{
    const int row = blockIdx.x;
    const int tid = threadIdx.x;
    const long long base = (long long)row * D + tid * VEC;

    // Load 4 floats for this thread
    float4 v = *reinterpret_cast<const float4*>(x + base);

    // Per-thread partial sums
    float s  = v.x + v.y + v.z + v.w;
    float ss = v.x * v.x + v.y * v.y + v.z * v.z + v.w * v.w;

    // Warp reduction
    #pragma unroll
    for (int off = 16; off > 0; off >>= 1) {
        s  += __shfl_xor_sync(0xFFFFFFFFu, s,  off);
        ss += __shfl_xor_sync(0xFFFFFFFFu, ss, off);
    }

    // Cross-warp reduction via shared memory (8 warps)
    __shared__ float sh_s[8];
    __shared__ float sh_ss[8];
    __shared__ float sh_mean, sh_rstd;

    const int warp = tid >> 5;
    const int lane = tid & 31;
    if (lane == 0) {
        sh_s[warp]  = s;
        sh_ss[warp] = ss;
    }
    __syncthreads();

    if (warp == 0) {
        float ws  = (lane < 8) ? sh_s[lane]  : 0.0f;
        float wss = (lane < 8) ? sh_ss[lane] : 0.0f;
        #pragma unroll
        for (int off = 4; off > 0; off >>= 1) {
            ws  += __shfl_xor_sync(0xFFFFFFFFu, ws,  off);
            wss += __shfl_xor_sync(0xFFFFFFFFu, wss, off);
        }
        if (lane == 0) {
            const float inv_d = 1.0f / (float)D;
            float mean = ws * inv_d;
            // var = E[x^2] - mean^2  (algebraically equal to reference's
            // mean((x-mean)^2); fp32 rounding diff is far below 1e-3 rel tol)
            float var = wss * inv_d - mean * mean;
            float a = var + EPS;
            // Reference's recurrence: divisor is ALWAYS a, not the iterate.
            float t;
            t = (a / a + a) * 0.5f;   // l1
            t = (t / a + a) * 0.5f;   // l2
            t = (t / a + a) * 0.5f;   // l3
            t = (t / a + a) * 0.5f;   // std
            sh_mean = mean;
            sh_rstd = 1.0f / t;
        }
    }
    __syncthreads();

    const float mean = sh_mean;
    const float rstd = sh_rstd;

    // Weight/bias for this thread's 4 columns (L2-resident, broadcast-friendly)
    float4 w = *reinterpret_cast<const float4*>(weight + tid * VEC);
    float4 b = *reinterpret_cast<const float4*>(bias   + tid * VEC);

    float4 o;
    o.x = (v.x - mean) * rstd * w.x + b.x;
    o.y = (v.y - mean) * rstd * w.y + b.y;
    o.z = (v.z - mean) * rstd * w.z + b.z;
    o.w = (v.w - mean) * rstd * w.w + b.w;

    *reinterpret_cast<float4*>(out + base) = o;
}

extern "C" void kernel_launch(void* const* d_in, const int* in_sizes, int n_in,
                              void* d_out, int out_size) {
    const float* x      = (const float*)d_in[0];
    const float* weight = (const float*)d_in[1];
    const float* bias   = (const float*)d_in[2];
    float* out          = (float*)d_out;

    const int rows = in_sizes[0] / D;   // 4*8192 = 32768
    qlayernorm_kernel<<<rows, THREADS>>>(x, weight, bias, out);
}

// round 3
// speedup vs baseline: 1.2266x; 1.2266x over previous
#include <cuda_runtime.h>

// QLayerNorm: B=4, S=8192, D=1024, fp32.
// One WARP per row. 8 warps (256 threads) per CTA -> 8 rows/CTA, grid=4096.
// Each lane loads 8 float4 (32 floats) = full row held in registers across
// the warp. Reduction is a pure shfl-xor butterfly (no smem, no barriers).
// Every lane ends with the full sums and computes mean/std redundantly,
// then writes its 8 float4 with fused (x-mean)*rstd*w + b.
//
// Reference's std recurrence (divisor is ALWAYS a, not the iterate):
//   l1=(a/a+a)*.5 ; l2=(l1/a+a)*.5 ; l3=(l2/a+a)*.5 ; std=(l3/a+a)*.5

#define D 1024
#define WARPS_PER_CTA 8
#define THREADS (WARPS_PER_CTA * 32)
#define VPL 8            // float4 loads per lane (D / (32*4))
#define EPS 5e-05f

__global__ __launch_bounds__(THREADS) void qlayernorm_kernel(
    const float* __restrict__ x,
    const float* __restrict__ weight,
    const float* __restrict__ bias,
    float* __restrict__ out)
{
    const int warp = threadIdx.x >> 5;
    const int lane = threadIdx.x & 31;
    const int row  = blockIdx.x * WARPS_PER_CTA + warp;

    const float* xr = x   + (long long)row * D;
    float*       orow = out + (long long)row * D;

    // Front-batched loads: 8 independent float4 -> 32 outstanding lines/warp
    float4 v[VPL];
    #pragma unroll
    for (int i = 0; i < VPL; i++) {
        v[i] = *reinterpret_cast<const float4*>(xr + (i * 32 + lane) * 4);
    }

    // Per-lane partial sums
    float s = 0.0f, ss = 0.0f;
    #pragma unroll
    for (int i = 0; i < VPL; i++) {
        s  += v[i].x + v[i].y + v[i].z + v[i].w;
        ss += v[i].x * v[i].x + v[i].y * v[i].y
            + v[i].z * v[i].z + v[i].w * v[i].w;
    }

    // Butterfly reduction: every lane ends with the full row sums
    #pragma unroll
    for (int off = 16; off > 0; off >>= 1) {
        s  += __shfl_xor_sync(0xFFFFFFFFu, s,  off);
        ss += __shfl_xor_sync(0xFFFFFFFFu, ss, off);
    }

    // Redundant per-lane scalar epilogue (FMA pipe is idle anyway)
    const float inv_d = 1.0f / (float)D;
    float mean = s * inv_d;
    float var  = ss * inv_d - mean * mean;
    float a = var + EPS;
    float t;
    t = (a / a + a) * 0.5f;   // l1
    t = (t / a + a) * 0.5f;   // l2
    t = (t / a + a) * 0.5f;   // l3
    t = (t / a + a) * 0.5f;   // std
    const float rstd = 1.0f / t;

    // Fused normalize + affine, 8 float4 stores
    #pragma unroll
    for (int i = 0; i < VPL; i++) {
        const int col = (i * 32 + lane) * 4;
        float4 w = *reinterpret_cast<const float4*>(weight + col);
        float4 b = *reinterpret_cast<const float4*>(bias   + col);
        float4 o;
        o.x = (v[i].x - mean) * rstd * w.x + b.x;
        o.y = (v[i].y - mean) * rstd * w.y + b.y;
        o.z = (v[i].z - mean) * rstd * w.z + b.z;
        o.w = (v[i].w - mean) * rstd * w.w + b.w;
        *reinterpret_cast<float4*>(orow + col) = o;
    }
}

extern "C" void kernel_launch(void* const* d_in, const int* in_sizes, int n_in,
                              void* d_out, int out_size) {
    const float* x      = (const float*)d_in[0];
    const float* weight = (const float*)d_in[1];
    const float* bias   = (const float*)d_in[2];
    float* out          = (float*)d_out;

    const int rows = in_sizes[0] / D;                 // 32768
    const int grid = rows / WARPS_PER_CTA;            // 4096
    qlayernorm_kernel<<<grid, THREADS>>>(x, weight, bias, out);
}